// round 1
// baseline (speedup 1.0000x reference)
#include <cuda_runtime.h>
#include <math.h>

#define B_ 16
#define HW 4096          // 64*64
#define CD 32
#define DIMX 512
#define NSCALES 14
#define OUT_ELEMS (B_*DIMX*HW)   // 33554432

#define INV_SQRT32 0.17677669529663687f
#define ACOEF 70.710678118654755f   // 4 * 100 / sqrt(32); p = sigmoid(-ACOEF*z)

__device__ float g_r [B_*HW*CD];   // residual, token-major (b, p, d)
__device__ float g_qo[B_*HW*CD];   // accumulated quantized, token-major
__device__ float g_q [B_*HW*CD];   // per-scale quantized tokens (scale resolution)
__device__ float g_acc[NSCALES][34];  // [0..31]=sum p per bit, [32]=sum H, [33]=sum commit

__constant__ int c_sched[NSCALES] = {1,2,3,4,5,7,9,12,16,21,27,36,48,64};

// ---------------------------------------------------------------- init
__global__ void init_kernel() {
    int t = threadIdx.x;
    if (t < NSCALES * 34) ((float*)g_acc)[t] = 0.0f;
}

// ---------------------------------------------------------------- proj_in
// r[b,p,d] = sum_c x[b,c,p] * w_in[c,d] + b_in[d]
__global__ void proj_in_kernel(const float* __restrict__ x,
                               const float* __restrict__ w_in,
                               const float* __restrict__ b_in) {
    extern __shared__ float s_w[];   // 512*32 floats
    int tid = threadIdx.x;
    for (int i = tid; i < DIMX * CD; i += blockDim.x) s_w[i] = w_in[i];
    __syncthreads();

    int b = blockIdx.x >> 4;                     // 16 blocks per batch image
    int p = ((blockIdx.x & 15) << 8) + tid;      // 256 pixels per block
    const float* xp = x + ((size_t)b * DIMX) * HW + p;

    float acc[CD];
#pragma unroll
    for (int d = 0; d < CD; d++) acc[d] = b_in[d];

#pragma unroll 4
    for (int c = 0; c < DIMX; c++) {
        float xv = xp[(size_t)c * HW];
        const float4* w4 = (const float4*)(s_w + c * CD);
#pragma unroll
        for (int q = 0; q < 8; q++) {
            float4 w = w4[q];
            acc[4*q+0] += xv * w.x;
            acc[4*q+1] += xv * w.y;
            acc[4*q+2] += xv * w.z;
            acc[4*q+3] += xv * w.w;
        }
    }
    float4* outp = (float4*)(g_r + ((size_t)(b * HW + p)) * CD);
#pragma unroll
    for (int q = 0; q < 8; q++)
        outp[q] = make_float4(acc[4*q], acc[4*q+1], acc[4*q+2], acc[4*q+3]);
}

// ---------------------------------------------------------------- BSQ math (per lane = one bit d)
__device__ __forceinline__ void bsq_lane(float ir, float& z, float& p, float& H,
                                         float& qv, float& cterm) {
    float n2 = ir * ir;
#pragma unroll
    for (int o = 16; o > 0; o >>= 1) n2 += __shfl_xor_sync(0xFFFFFFFFu, n2, o);
    float norm = sqrtf(n2);
    z = ir / fmaxf(norm, 1e-12f);
    p = 1.0f / (1.0f + expf(ACOEF * z));          // sigmoid(-ACOEF*z)
    float lp = logf(p + 1e-8f);
    float lq = logf(1.0f - p + 1e-8f);
    H = -(p * lp + (1.0f - p) * lq);
    qv = (z > 0.0f) ? INV_SQRT32 : -INV_SQRT32;
    float dz = z - qv;
    cterm = dz * dz;
}

// ---------------------------------------------------------------- bsq, small scales (block per token)
__global__ void bsq_small_kernel(int ph, int pw, int sidx) {
    __shared__ float s_part[8][CD];
    int t = blockIdx.x;
    int lane = threadIdx.x & 31;
    int rep  = threadIdx.x >> 5;
    int np = ph * pw;
    int b  = t / np;
    int ij = t - b * np;
    int i  = ij / pw;
    int j  = ij - i * pw;
    int sh = (i * 64) / ph,       eh = ((i + 1) * 64 + ph - 1) / ph;
    int sw = (j * 64) / pw,       ew = ((j + 1) * 64 + pw - 1) / pw;

    const float* rb = g_r + ((size_t)b * HW) * CD + lane;
    float sum = 0.0f;
    for (int y = sh + rep; y < eh; y += 8) {
        const float* row = rb + (size_t)(y * 64) * CD;
#pragma unroll 4
        for (int x2 = sw; x2 < ew; x2++)
            sum += row[(size_t)x2 * CD];
    }
    s_part[rep][lane] = sum;
    __syncthreads();

    if (rep == 0) {
        float s = s_part[0][lane];
#pragma unroll
        for (int r2 = 1; r2 < 8; r2++) s += s_part[r2][lane];
        float ir = s / (float)((eh - sh) * (ew - sw));

        float z, p, H, qv, cterm;
        bsq_lane(ir, z, p, H, qv, cterm);
        g_q[(size_t)t * CD + lane] = qv;

        float hc = H, cc = cterm;
#pragma unroll
        for (int o = 16; o > 0; o >>= 1) {
            hc += __shfl_xor_sync(0xFFFFFFFFu, hc, o);
            cc += __shfl_xor_sync(0xFFFFFFFFu, cc, o);
        }
        atomicAdd(&g_acc[sidx][lane], p);
        if (lane == 0) {
            atomicAdd(&g_acc[sidx][32], hc);
            atomicAdd(&g_acc[sidx][33], cc);
        }
    }
}

// ---------------------------------------------------------------- bsq, large scales (warp per token)
__global__ void bsq_large_kernel(int ph, int pw, int sidx) {
    __shared__ float s_prob[CD];
    __shared__ float s_hc[2];
    int lane = threadIdx.x & 31;
    int warp = blockIdx.x * (blockDim.x >> 5) + (threadIdx.x >> 5);
    int nw   = gridDim.x * (blockDim.x >> 5);
    int np = ph * pw, ntok = B_ * np;

    if (threadIdx.x < CD) s_prob[threadIdx.x] = 0.0f;
    if (threadIdx.x < 2)  s_hc[threadIdx.x] = 0.0f;
    __syncthreads();

    float pa = 0.0f, ha = 0.0f, ca = 0.0f;
    for (int t = warp; t < ntok; t += nw) {
        int b  = t / np;
        int ij = t - b * np;
        int i  = ij / pw;
        int j  = ij - i * pw;
        int sh = (i * 64) / ph,  eh = ((i + 1) * 64 + ph - 1) / ph;
        int sw = (j * 64) / pw,  ew = ((j + 1) * 64 + pw - 1) / pw;

        const float* rb = g_r + ((size_t)b * HW) * CD + lane;
        float sum = 0.0f;
        for (int y = sh; y < eh; y++) {
            const float* row = rb + (size_t)(y * 64) * CD;
#pragma unroll 2
            for (int x2 = sw; x2 < ew; x2++)
                sum += row[(size_t)x2 * CD];
        }
        float ir = sum / (float)((eh - sh) * (ew - sw));

        float z, p, H, qv, cterm;
        bsq_lane(ir, z, p, H, qv, cterm);
        g_q[(size_t)t * CD + lane] = qv;
        pa += p; ha += H; ca += cterm;
    }
    // block-level reduce, then one atomic set per block
    atomicAdd(&s_prob[lane], pa);
#pragma unroll
    for (int o = 16; o > 0; o >>= 1) {
        ha += __shfl_xor_sync(0xFFFFFFFFu, ha, o);
        ca += __shfl_xor_sync(0xFFFFFFFFu, ca, o);
    }
    if (lane == 0) {
        atomicAdd(&s_hc[0], ha);
        atomicAdd(&s_hc[1], ca);
    }
    __syncthreads();
    if (threadIdx.x < CD) atomicAdd(&g_acc[sidx][threadIdx.x], s_prob[threadIdx.x]);
    if (threadIdx.x == 32) atomicAdd(&g_acc[sidx][32], s_hc[0]);
    if (threadIdx.x == 33) atomicAdd(&g_acc[sidx][33], s_hc[1]);
}

// ---------------------------------------------------------------- bilinear up + residual update
// (identity path for ph=pw=64 falls out naturally: frac weights become 0)
__global__ void up_kernel(int ph, int pw, int first) {
    int lane = threadIdx.x & 31;
    int warp = blockIdx.x * (blockDim.x >> 5) + (threadIdx.x >> 5);
    int nw   = gridDim.x * (blockDim.x >> 5);
    float scaleh = (float)ph * (1.0f / 64.0f);
    float scalew = (float)pw * (1.0f / 64.0f);

    for (int pix = warp; pix < B_ * HW; pix += nw) {
        int b  = pix >> 12;
        int hw = pix & (HW - 1);
        int h  = hw >> 6, w = hw & 63;

        float srch = fminf(fmaxf((h + 0.5f) * scaleh - 0.5f, 0.0f), (float)(ph - 1));
        int i0 = (int)srch;  float wh = srch - (float)i0;  int i1 = min(i0 + 1, ph - 1);
        float srcw = fminf(fmaxf((w + 0.5f) * scalew - 0.5f, 0.0f), (float)(pw - 1));
        int j0 = (int)srcw;  float ww = srcw - (float)j0;  int j1 = min(j0 + 1, pw - 1);

        const float* qb = g_q + ((size_t)b * ph * pw) * CD + lane;
        float q00 = qb[(size_t)(i0 * pw + j0) * CD];
        float q01 = qb[(size_t)(i0 * pw + j1) * CD];
        float q10 = qb[(size_t)(i1 * pw + j0) * CD];
        float q11 = qb[(size_t)(i1 * pw + j1) * CD];
        float v = (1.0f - wh) * ((1.0f - ww) * q00 + ww * q01)
                +         wh  * ((1.0f - ww) * q10 + ww * q11);

        size_t o = (size_t)pix * CD + lane;
        g_r[o] -= v;
        g_qo[o] = first ? v : (g_qo[o] + v);
    }
}

// ---------------------------------------------------------------- losses
__global__ void finalize_kernel(float* __restrict__ loss_out) {
    int s = threadIdx.x >> 5;
    int lane = threadIdx.x & 31;
    if (s >= NSCALES) return;
    int ph = c_sched[s];
    float n = (float)(B_ * ph * ph);

    float ap = g_acc[s][lane] / n;
    float H = -(ap * logf(ap + 1e-8f) + (1.0f - ap) * logf(1.0f - ap + 1e-8f));
#pragma unroll
    for (int o = 16; o > 0; o >>= 1) H += __shfl_xor_sync(0xFFFFFFFFu, H, o);
    if (lane == 0) {
        float ps = g_acc[s][32] / n;            // persample entropy mean
        float cm = g_acc[s][33] / (n * 32.0f);  // commitment mean
        float loss = (ps - H) * (0.1f / 100.0f) + 0.25f * cm;
        loss_out[s] = loss;
    }
}

// ---------------------------------------------------------------- proj_out
// out[b,c,p] = sum_d qo[b,p,d] * w_out[d,c] + b_out[c]
__global__ void proj_out_kernel(const float* __restrict__ w_out,
                                const float* __restrict__ b_out,
                                float* __restrict__ out) {
    extern __shared__ float s[];
    float* s_w = s;             // [32][512]
    float* s_b = s + CD * DIMX; // [512]
    int tid = threadIdx.x;
    for (int i = tid; i < CD * DIMX; i += blockDim.x) s_w[i] = w_out[i];
    for (int i = tid; i < DIMX; i += blockDim.x) s_b[i] = b_out[i];
    __syncthreads();

    int b = blockIdx.x >> 4;
    int p = ((blockIdx.x & 15) << 8) + tid;

    float q[CD];
    const float4* qp = (const float4*)(g_qo + ((size_t)(b * HW + p)) * CD);
#pragma unroll
    for (int i = 0; i < 8; i++) {
        float4 v = qp[i];
        q[4*i+0] = v.x; q[4*i+1] = v.y; q[4*i+2] = v.z; q[4*i+3] = v.w;
    }

    float* op = out + ((size_t)b * DIMX) * HW + p;
    for (int c = 0; c < DIMX; c += 4) {
        float a0 = s_b[c], a1 = s_b[c+1], a2 = s_b[c+2], a3 = s_b[c+3];
#pragma unroll
        for (int d = 0; d < CD; d++) {
            float4 wv = *(const float4*)(s_w + d * DIMX + c);
            a0 += q[d] * wv.x;
            a1 += q[d] * wv.y;
            a2 += q[d] * wv.z;
            a3 += q[d] * wv.w;
        }
        op[(size_t)(c + 0) * HW] = a0;
        op[(size_t)(c + 1) * HW] = a1;
        op[(size_t)(c + 2) * HW] = a2;
        op[(size_t)(c + 3) * HW] = a3;
    }
}

// ---------------------------------------------------------------- launch
extern "C" void kernel_launch(void* const* d_in, const int* in_sizes, int n_in,
                              void* d_out, int out_size) {
    const float* x     = (const float*)d_in[0];
    const float* w_in  = (const float*)d_in[1];
    const float* b_in  = (const float*)d_in[2];
    const float* w_out = (const float*)d_in[3];
    const float* b_out = (const float*)d_in[4];
    float* out = (float*)d_out;

    static const int sched[NSCALES] = {1,2,3,4,5,7,9,12,16,21,27,36,48,64};

    cudaFuncSetAttribute(proj_in_kernel, cudaFuncAttributeMaxDynamicSharedMemorySize, 64 * 1024);
    cudaFuncSetAttribute(proj_out_kernel, cudaFuncAttributeMaxDynamicSharedMemorySize, 68 * 1024);

    init_kernel<<<1, 512>>>();
    proj_in_kernel<<<256, 256, 64 * 1024>>>(x, w_in, b_in);

    for (int s = 0; s < NSCALES; s++) {
        int ph = sched[s], pw = sched[s];
        int ntok = B_ * ph * pw;
        if (ntok < 1024) {
            bsq_small_kernel<<<ntok, 256>>>(ph, pw, s);
        } else {
            int blocks = (ntok + 7) / 8;
            if (blocks > 2048) blocks = 2048;
            bsq_large_kernel<<<blocks, 256>>>(ph, pw, s);
        }
        up_kernel<<<1024, 256>>>(ph, pw, s == 0 ? 1 : 0);
    }

    if (out_size >= OUT_ELEMS + NSCALES)
        finalize_kernel<<<1, NSCALES * 32>>>(out + OUT_ELEMS);

    proj_out_kernel<<<256, 256, 68 * 1024>>>(w_out, b_out, out);
}

// round 2
// speedup vs baseline: 1.1080x; 1.1080x over previous
#include <cuda_runtime.h>
#include <math.h>

#define B_ 16
#define HW 4096          // 64*64
#define CD 32
#define DIMX 512
#define NSCALES 14
#define OUT_ELEMS (B_*DIMX*HW)   // 33554432

#define INV_SQRT32 0.17677669529663687f
#define ACOEF 70.710678118654755f   // 4*100/sqrt(32); p = sigmoid(-ACOEF*z)

__device__ float g_r0[B_*HW*CD];     // original projection (token-major b,p,d)
__device__ float g_r [B_*HW*CD];     // residual
__device__ float g_q [B_*HW*CD];     // per-scale quantized tokens
__device__ float g_pool[B_*9*CD];    // pooled sums for ph<=3 (max 144 tokens)
__device__ float g_acc[NSCALES][34]; // [0..31]=sum p, [32]=sum H, [33]=sum commit

__constant__ int c_sched[NSCALES] = {1,2,3,4,5,7,9,12,16,21,27,36,48,64};

// ---------------------------------------------------------------- f32x2 helpers
__device__ __forceinline__ unsigned long long pk2(float x, float y) {
    unsigned long long r;
    asm("mov.b64 %0, {%1, %2};" : "=l"(r) : "f"(x), "f"(y));
    return r;
}
__device__ __forceinline__ unsigned long long fma2(unsigned long long a,
                                                   unsigned long long b,
                                                   unsigned long long c) {
    unsigned long long d;
    asm("fma.rn.f32x2 %0, %1, %2, %3;" : "=l"(d) : "l"(a), "l"(b), "l"(c));
    return d;
}
__device__ __forceinline__ void upk2(unsigned long long v, float& lo, float& hi) {
    asm("mov.b64 {%0, %1}, %2;" : "=f"(lo), "=f"(hi) : "l"(v));
}

// ---------------------------------------------------------------- init
__global__ void init_kernel() {
    int t = blockIdx.x * blockDim.x + threadIdx.x;
    if (t < NSCALES * 34) ((float*)g_acc)[t] = 0.0f;
    if (t < B_ * 9 * CD) g_pool[t] = 0.0f;
}

// ---------------------------------------------------------------- proj_in
// r[b,p,d] = sum_c x[b,c,p] * w_in[c,d] + b_in[d]   (FFMA2, 2 px/thread)
__global__ __launch_bounds__(128) void proj_in_kernel(
        const float* __restrict__ x,
        const float* __restrict__ w_in,
        const float* __restrict__ b_in) {
    extern __shared__ float s_w[];   // [512][32]
    int tid = threadIdx.x;
    for (int i = tid; i < DIMX * CD; i += 128) s_w[i] = w_in[i];
    __syncthreads();

    int b = blockIdx.x >> 4;                      // 16 blocks per image
    int base = (blockIdx.x & 15) << 8;            // 256 px per block
    int p0 = base + tid, p1 = p0 + 128;
    const float* xp0 = x + ((size_t)b * DIMX) * HW + p0;
    const float* xp1 = x + ((size_t)b * DIMX) * HW + p1;

    unsigned long long a0[16], a1[16];            // dim-pair packed accumulators
#pragma unroll
    for (int q = 0; q < 16; q++) {
        unsigned long long bi = pk2(b_in[2*q], b_in[2*q+1]);
        a0[q] = bi; a1[q] = bi;
    }

#pragma unroll 4
    for (int c = 0; c < DIMX; c++) {
        float f0 = xp0[(size_t)c * HW];
        float f1 = xp1[(size_t)c * HW];
        unsigned long long X0 = pk2(f0, f0);
        unsigned long long X1 = pk2(f1, f1);
        const ulonglong2* row = (const ulonglong2*)(s_w + c * CD);
#pragma unroll
        for (int r = 0; r < 8; r++) {
            ulonglong2 w2 = row[r];               // dims 4r..4r+3
            a0[2*r]   = fma2(X0, w2.x, a0[2*r]);
            a0[2*r+1] = fma2(X0, w2.y, a0[2*r+1]);
            a1[2*r]   = fma2(X1, w2.x, a1[2*r]);
            a1[2*r+1] = fma2(X1, w2.y, a1[2*r+1]);
        }
    }
    size_t o0 = ((size_t)(b * HW + p0)) * CD;
    size_t o1 = ((size_t)(b * HW + p1)) * CD;
#pragma unroll
    for (int k = 0; k < 8; k++) {
        ulonglong2 v0; v0.x = a0[2*k]; v0.y = a0[2*k+1];
        ulonglong2 v1; v1.x = a1[2*k]; v1.y = a1[2*k+1];
        ((ulonglong2*)(g_r0 + o0))[k] = v0;
        ((ulonglong2*)(g_r  + o0))[k] = v0;
        ((ulonglong2*)(g_r0 + o1))[k] = v1;
        ((ulonglong2*)(g_r  + o1))[k] = v1;
    }
}

// ---------------------------------------------------------------- BSQ per-lane math
__device__ __forceinline__ void bsq_lane(float ir, float& z, float& p, float& H,
                                         float& qv, float& cterm) {
    float n2 = ir * ir;
#pragma unroll
    for (int o = 16; o > 0; o >>= 1) n2 += __shfl_xor_sync(0xFFFFFFFFu, n2, o);
    float norm = sqrtf(n2);
    z = ir / fmaxf(norm, 1e-12f);
    p = 1.0f / (1.0f + expf(ACOEF * z));
    float lp = logf(p + 1e-8f);
    float lq = logf(1.0f - p + 1e-8f);
    H = -(p * lp + (1.0f - p) * lq);
    qv = (z > 0.0f) ? INV_SQRT32 : -INV_SQRT32;
    float dz = z - qv;
    cterm = dz * dz;
}

// ---------------------------------------------------------------- 2-stage pooling (ph<=3)
__global__ void pool_kernel(int ph, int S) {
    __shared__ float sp[8][CD];
    int t = blockIdx.x / S, slice = blockIdx.x - t * S;
    int lane = threadIdx.x & 31, rep = threadIdx.x >> 5;
    int np = ph * ph;
    int b = t / np, ij = t - b * np, i = ij / ph, j = ij - i * ph;
    int sh = (i * 64) / ph, eh = ((i + 1) * 64 + ph - 1) / ph;
    int sw = (j * 64) / ph, ew = ((j + 1) * 64 + ph - 1) / ph;

    const float* rb = g_r + ((size_t)b * HW) * CD + lane;
    float sum = 0.0f;
    for (int y = sh + slice * 8 + rep; y < eh; y += S * 8) {
        const float* row = rb + (size_t)(y * 64) * CD;
#pragma unroll 4
        for (int x2 = sw; x2 < ew; x2++) sum += row[(size_t)x2 * CD];
    }
    sp[rep][lane] = sum;
    __syncthreads();
    if (rep == 0) {
        float s = sp[0][lane];
#pragma unroll
        for (int r = 1; r < 8; r++) s += sp[r][lane];
        atomicAdd(&g_pool[t * CD + lane], s);
    }
}

__global__ void bsq_finish_kernel(int ph, int sidx) {
    int gw = blockIdx.x * (blockDim.x >> 5) + (threadIdx.x >> 5);
    int lane = threadIdx.x & 31;
    int np = ph * ph, ntok = B_ * np;
    if (gw >= ntok) return;
    int t = gw;
    int b = t / np, ij = t - b * np, i = ij / ph, j = ij - i * ph;
    int sh = (i * 64) / ph, eh = ((i + 1) * 64 + ph - 1) / ph;
    int sw = (j * 64) / ph, ew = ((j + 1) * 64 + ph - 1) / ph;

    float s = g_pool[t * CD + lane];
    g_pool[t * CD + lane] = 0.0f;                 // restore zero invariant
    float ir = s / (float)((eh - sh) * (ew - sw));

    float z, p, H, qv, cterm;
    bsq_lane(ir, z, p, H, qv, cterm);
    g_q[(size_t)t * CD + lane] = qv;

    float hc = H, cc = cterm;
#pragma unroll
    for (int o = 16; o > 0; o >>= 1) {
        hc += __shfl_xor_sync(0xFFFFFFFFu, hc, o);
        cc += __shfl_xor_sync(0xFFFFFFFFu, cc, o);
    }
    atomicAdd(&g_acc[sidx][lane], p);
    if (lane == 0) {
        atomicAdd(&g_acc[sidx][32], hc);
        atomicAdd(&g_acc[sidx][33], cc);
    }
}

// ---------------------------------------------------------------- bsq, mid scales (block/token)
__global__ void bsq_small_kernel(int ph, int pw, int sidx) {
    __shared__ float s_part[8][CD];
    int t = blockIdx.x;
    int lane = threadIdx.x & 31;
    int rep  = threadIdx.x >> 5;
    int np = ph * pw;
    int b  = t / np;
    int ij = t - b * np;
    int i  = ij / pw;
    int j  = ij - i * pw;
    int sh = (i * 64) / ph, eh = ((i + 1) * 64 + ph - 1) / ph;
    int sw = (j * 64) / pw, ew = ((j + 1) * 64 + pw - 1) / pw;

    const float* rb = g_r + ((size_t)b * HW) * CD + lane;
    float sum = 0.0f;
    for (int y = sh + rep; y < eh; y += 8) {
        const float* row = rb + (size_t)(y * 64) * CD;
#pragma unroll 4
        for (int x2 = sw; x2 < ew; x2++)
            sum += row[(size_t)x2 * CD];
    }
    s_part[rep][lane] = sum;
    __syncthreads();

    if (rep == 0) {
        float s = s_part[0][lane];
#pragma unroll
        for (int r2 = 1; r2 < 8; r2++) s += s_part[r2][lane];
        float ir = s / (float)((eh - sh) * (ew - sw));

        float z, p, H, qv, cterm;
        bsq_lane(ir, z, p, H, qv, cterm);
        g_q[(size_t)t * CD + lane] = qv;

        float hc = H, cc = cterm;
#pragma unroll
        for (int o = 16; o > 0; o >>= 1) {
            hc += __shfl_xor_sync(0xFFFFFFFFu, hc, o);
            cc += __shfl_xor_sync(0xFFFFFFFFu, cc, o);
        }
        atomicAdd(&g_acc[sidx][lane], p);
        if (lane == 0) {
            atomicAdd(&g_acc[sidx][32], hc);
            atomicAdd(&g_acc[sidx][33], cc);
        }
    }
}

// ---------------------------------------------------------------- bsq, large scales (warp/token)
__global__ void bsq_large_kernel(int ph, int pw, int sidx) {
    __shared__ float s_prob[CD];
    __shared__ float s_hc[2];
    int lane = threadIdx.x & 31;
    int warp = blockIdx.x * (blockDim.x >> 5) + (threadIdx.x >> 5);
    int nw   = gridDim.x * (blockDim.x >> 5);
    int np = ph * pw, ntok = B_ * np;

    if (threadIdx.x < CD) s_prob[threadIdx.x] = 0.0f;
    if (threadIdx.x < 2)  s_hc[threadIdx.x] = 0.0f;
    __syncthreads();

    float pa = 0.0f, ha = 0.0f, ca = 0.0f;
    for (int t = warp; t < ntok; t += nw) {
        int b  = t / np;
        int ij = t - b * np;
        int i  = ij / pw;
        int j  = ij - i * pw;
        int sh = (i * 64) / ph,  eh = ((i + 1) * 64 + ph - 1) / ph;
        int sw = (j * 64) / pw,  ew = ((j + 1) * 64 + pw - 1) / pw;

        const float* rb = g_r + ((size_t)b * HW) * CD + lane;
        float sum = 0.0f;
        for (int y = sh; y < eh; y++) {
            const float* row = rb + (size_t)(y * 64) * CD;
#pragma unroll 2
            for (int x2 = sw; x2 < ew; x2++)
                sum += row[(size_t)x2 * CD];
        }
        float ir = sum / (float)((eh - sh) * (ew - sw));

        float z, p, H, qv, cterm;
        bsq_lane(ir, z, p, H, qv, cterm);
        g_q[(size_t)t * CD + lane] = qv;
        pa += p; ha += H; ca += cterm;
    }
    atomicAdd(&s_prob[lane], pa);
#pragma unroll
    for (int o = 16; o > 0; o >>= 1) {
        ha += __shfl_xor_sync(0xFFFFFFFFu, ha, o);
        ca += __shfl_xor_sync(0xFFFFFFFFu, ca, o);
    }
    if (lane == 0) {
        atomicAdd(&s_hc[0], ha);
        atomicAdd(&s_hc[1], ca);
    }
    __syncthreads();
    if (threadIdx.x < CD) atomicAdd(&g_acc[sidx][threadIdx.x], s_prob[threadIdx.x]);
    if (threadIdx.x == 32) atomicAdd(&g_acc[sidx][32], s_hc[0]);
    if (threadIdx.x == 33) atomicAdd(&g_acc[sidx][33], s_hc[1]);
}

// ---------------------------------------------------------------- bilinear up + r update (no qo)
__global__ void up_kernel(int ph, int pw) {
    int lane = threadIdx.x & 31;
    int warp = blockIdx.x * (blockDim.x >> 5) + (threadIdx.x >> 5);
    int nw   = gridDim.x * (blockDim.x >> 5);
    float scaleh = (float)ph * (1.0f / 64.0f);
    float scalew = (float)pw * (1.0f / 64.0f);

    for (int pix = warp; pix < B_ * HW; pix += nw) {
        int b  = pix >> 12;
        int hw = pix & (HW - 1);
        int h  = hw >> 6, w = hw & 63;

        float srch = fminf(fmaxf((h + 0.5f) * scaleh - 0.5f, 0.0f), (float)(ph - 1));
        int i0 = (int)srch;  float wh = srch - (float)i0;  int i1 = min(i0 + 1, ph - 1);
        float srcw = fminf(fmaxf((w + 0.5f) * scalew - 0.5f, 0.0f), (float)(pw - 1));
        int j0 = (int)srcw;  float ww = srcw - (float)j0;  int j1 = min(j0 + 1, pw - 1);

        const float* qb = g_q + ((size_t)b * ph * pw) * CD + lane;
        float q00 = qb[(size_t)(i0 * pw + j0) * CD];
        float q01 = qb[(size_t)(i0 * pw + j1) * CD];
        float q10 = qb[(size_t)(i1 * pw + j0) * CD];
        float q11 = qb[(size_t)(i1 * pw + j1) * CD];
        float v = (1.0f - wh) * ((1.0f - ww) * q00 + ww * q01)
                +         wh  * ((1.0f - ww) * q10 + ww * q11);

        size_t o = (size_t)pix * CD + lane;
        g_r[o] -= v;
    }
}

// ---------------------------------------------------------------- losses
__global__ void finalize_kernel(float* __restrict__ loss_out) {
    int s = threadIdx.x >> 5;
    int lane = threadIdx.x & 31;
    if (s >= NSCALES) return;
    int ph = c_sched[s];
    float n = (float)(B_ * ph * ph);

    float ap = g_acc[s][lane] / n;
    float H = -(ap * logf(ap + 1e-8f) + (1.0f - ap) * logf(1.0f - ap + 1e-8f));
#pragma unroll
    for (int o = 16; o > 0; o >>= 1) H += __shfl_xor_sync(0xFFFFFFFFu, H, o);
    if (lane == 0) {
        float ps = g_acc[s][32] / n;
        float cm = g_acc[s][33] / (n * 32.0f);
        float loss = (ps - H) * (0.1f / 100.0f) + 0.25f * cm;
        loss_out[s] = loss;
    }
}

// ---------------------------------------------------------------- proj_out
// qo = r0 - r + q64 ; out[b,c,p] = sum_d qo[d] * w_out[d,c] + b_out[c]
__global__ __launch_bounds__(128) void proj_out_kernel(
        const float* __restrict__ w_out,
        const float* __restrict__ b_out,
        float* __restrict__ out) {
    extern __shared__ float s[];
    float* s_wt = s;                 // transposed: [c][d] = w_out[d][c]  (64KB)
    float* s_b  = s + DIMX * CD;     // [512]
    int tid = threadIdx.x;
    for (int idx = tid; idx < DIMX * CD; idx += 128) {
        int c = idx >> 5, d = idx & 31;
        s_wt[c * CD + d] = w_out[d * DIMX + c];
    }
    for (int i = tid; i < DIMX; i += 128) s_b[i] = b_out[i];
    __syncthreads();

    int b = blockIdx.x >> 4;
    int base = (blockIdx.x & 15) << 8;
    int p0 = base + tid, p1 = p0 + 128;
    size_t o0 = ((size_t)(b * HW + p0)) * CD;
    size_t o1 = ((size_t)(b * HW + p1)) * CD;

    // qo = r0 - r + q64, packed as d-pairs
    unsigned long long Q0[16], Q1[16];
#pragma unroll
    for (int k = 0; k < 8; k++) {
        float4 a = ((const float4*)(g_r0 + o0))[k];
        float4 r = ((const float4*)(g_r  + o0))[k];
        float4 q = ((const float4*)(g_q  + o0))[k];
        Q0[2*k]   = pk2(a.x - r.x + q.x, a.y - r.y + q.y);
        Q0[2*k+1] = pk2(a.z - r.z + q.z, a.w - r.w + q.w);
        float4 a1 = ((const float4*)(g_r0 + o1))[k];
        float4 r1 = ((const float4*)(g_r  + o1))[k];
        float4 q1 = ((const float4*)(g_q  + o1))[k];
        Q1[2*k]   = pk2(a1.x - r1.x + q1.x, a1.y - r1.y + q1.y);
        Q1[2*k+1] = pk2(a1.z - r1.z + q1.z, a1.w - r1.w + q1.w);
    }

    float* op0 = out + ((size_t)b * DIMX) * HW + p0;
    float* op1 = out + ((size_t)b * DIMX) * HW + p1;

#pragma unroll 2
    for (int c = 0; c < DIMX; c++) {
        const ulonglong2* wrow = (const ulonglong2*)(s_wt + c * CD);
        unsigned long long a0e = 0, a0o = 0, a1e = 0, a1o = 0;
#pragma unroll
        for (int r = 0; r < 8; r++) {
            ulonglong2 W = wrow[r];            // dims 4r..4r+3
            a0e = fma2(Q0[2*r],   W.x, a0e);
            a0o = fma2(Q0[2*r+1], W.y, a0o);
            a1e = fma2(Q1[2*r],   W.x, a1e);
            a1o = fma2(Q1[2*r+1], W.y, a1o);
        }
        float lo, hi, s0, s1;
        upk2(a0e, lo, hi); s0 = lo + hi;
        upk2(a0o, lo, hi); s0 += lo + hi;
        upk2(a1e, lo, hi); s1 = lo + hi;
        upk2(a1o, lo, hi); s1 += lo + hi;
        float bias = s_b[c];
        op0[(size_t)c * HW] = s0 + bias;
        op1[(size_t)c * HW] = s1 + bias;
    }
}

// ---------------------------------------------------------------- launch
extern "C" void kernel_launch(void* const* d_in, const int* in_sizes, int n_in,
                              void* d_out, int out_size) {
    const float* x     = (const float*)d_in[0];
    const float* w_in  = (const float*)d_in[1];
    const float* b_in  = (const float*)d_in[2];
    const float* w_out = (const float*)d_in[3];
    const float* b_out = (const float*)d_in[4];
    float* out = (float*)d_out;

    static const int sched[NSCALES] = {1,2,3,4,5,7,9,12,16,21,27,36,48,64};
    static const int sl[4] = {0, 8, 4, 3};   // slices per token for ph 1,2,3

    cudaFuncSetAttribute(proj_in_kernel,  cudaFuncAttributeMaxDynamicSharedMemorySize, 66 * 1024);
    cudaFuncSetAttribute(proj_out_kernel, cudaFuncAttributeMaxDynamicSharedMemorySize, 68 * 1024);

    init_kernel<<<20, 256>>>();
    proj_in_kernel<<<256, 128, 64 * 1024>>>(x, w_in, b_in);

    for (int s = 0; s < NSCALES; s++) {
        int ph = sched[s];
        int ntok = B_ * ph * ph;
        if (ph <= 3) {
            int S = sl[ph];
            pool_kernel<<<ntok * S, 256>>>(ph, S);
            bsq_finish_kernel<<<(ntok + 7) / 8, 256>>>(ph, s);
        } else if (ntok < 1024) {
            bsq_small_kernel<<<ntok, 256>>>(ph, ph, s);
        } else {
            int blocks = (ntok + 7) / 8;
            if (blocks > 2048) blocks = 2048;
            bsq_large_kernel<<<blocks, 256>>>(ph, ph, s);
        }
        if (s < NSCALES - 1)
            up_kernel<<<1024, 256>>>(ph, ph);
    }

    if (out_size >= OUT_ELEMS + NSCALES)
        finalize_kernel<<<1, NSCALES * 32>>>(out + OUT_ELEMS);

    proj_out_kernel<<<256, 128, 68 * 1024>>>(w_out, b_out, out);
}